// round 5
// baseline (speedup 1.0000x reference)
#include <cuda_runtime.h>

#define BGRAPHS 64
#define NPG     1024
#define NTOT    (BGRAPHS * NPG)   // 65536
#define DIM     512
#define DROPN   512               // NPG - ceil(0.5*NPG)
#define PPARTS  16                // partial copies per graph (privatized reduce)
#define ECAP    (64 * 1024 * 32)  // dst16 cache capacity (expected E)

// ---- scratch (device globals: no allocation allowed) ----
__device__ float g_h[NTOT];
__device__ float g_norm[NTOT];
__device__ float g_wb[NTOT];
__device__ int   g_pdeg[PPARTS * NTOT];          // 4 MB partial degree hist
__device__ float g_pagg[PPARTS * NTOT];          // 4 MB partial agg sums
__device__ unsigned short g_dst16[ECAP];         // 4 MB compacted local dst

// ---------------------------------------------------------------------------
// Inline int64-vs-int32 probe: node indices < 2^17, so for int64 data every
// odd 32-bit word is zero. Deterministic; every CTA computes the same answer.
// ---------------------------------------------------------------------------
__device__ __forceinline__ int probe_is64(const void* p, long long nelem) {
    const unsigned* w = (const unsigned*)p;
    int lim = (nelem > 64) ? 128 : (int)(nelem * 2);
    int any = 0;
    for (int i = 1; i < lim; i += 2) any |= (w[i] != 0u);
    return any ? 0 : 1;
}

__device__ __forceinline__ int edge_idx(const void* p, long long e, int is64) {
    if (is64) return (int)((const long long*)p)[e];
    return ((const int*)p)[e];
}

// ---------------------------------------------------------------------------
// Degree partials: PPARTS CTAs per graph, shared int histogram, plain stores.
// Also compacts dst to uint16 local indices for the agg pass.
// ---------------------------------------------------------------------------
__global__ void k_deg_part(const void* __restrict__ dst, long long EPG,
                           int EPP, int use16, long long E) {
    __shared__ int sacc[NPG];
    __shared__ int s_is64;
    int g = blockIdx.x >> 4;
    int p = blockIdx.x & (PPARTS - 1);
    if (threadIdx.x == 0) s_is64 = probe_is64(dst, E);
    for (int j = threadIdx.x; j < NPG; j += blockDim.x) sacc[j] = 0;
    __syncthreads();

    const int is64 = s_is64;
    long long base = (long long)g * EPG + (long long)p * EPP;
    long long rem = EPG - (long long)p * EPP;
    int cnt = (rem < (long long)EPP) ? (rem > 0 ? (int)rem : 0) : EPP;

    for (int e = threadIdx.x; e < cnt; e += blockDim.x) {
        long long idx = base + e;
        int d = edge_idx(dst, idx, is64) & (NPG - 1);
        atomicAdd(&sacc[d], 1);
        if (use16) g_dst16[idx] = (unsigned short)d;
    }
    __syncthreads();

    int out = p * NTOT + g * NPG;
    for (int j = threadIdx.x; j < NPG; j += blockDim.x)
        g_pdeg[out + j] = sacc[j];
}

// ---------------------------------------------------------------------------
// norm[i] = deg^-0.5 (0 if isolated); deg = sum of 16 partials
// ---------------------------------------------------------------------------
__global__ void k_norm() {
    int i = blockIdx.x * blockDim.x + threadIdx.x;
    if (i >= NTOT) return;
    int c = 0;
#pragma unroll
    for (int p = 0; p < PPARTS; p++) c += g_pdeg[p * NTOT + i];
    g_norm[i] = (c > 0) ? rsqrtf((float)c) : 0.0f;
}

// ---------------------------------------------------------------------------
// h[n] = dot(features[n,:], weight) * norm[n].  FOUR rows per warp:
// 16 front-batched LDG.128 per lane for max memory-level parallelism.
// ---------------------------------------------------------------------------
__global__ void k_h(const float* __restrict__ feat,
                    const float* __restrict__ weight) {
    __shared__ float4 swt[DIM / 4];
    int t = threadIdx.x;
    if (t < DIM / 4) swt[t] = ((const float4*)weight)[t];
    __syncthreads();

    int warp = t >> 5, lane = t & 31;
    int row0 = (blockIdx.x * (blockDim.x >> 5) + warp) * 4;
    if (row0 >= NTOT) return;

    const float4* f0 = (const float4*)(feat + (long long)row0 * DIM);
    const float4* f1 = f0 + DIM / 4;
    const float4* f2 = f1 + DIM / 4;
    const float4* f3 = f2 + DIM / 4;
    float a0 = 0.f, a1 = 0.f, a2 = 0.f, a3 = 0.f;
#pragma unroll
    for (int k = 0; k < 4; k++) {
        int c = lane + 32 * k;
        float4 x0 = f0[c];
        float4 x1 = f1[c];
        float4 x2 = f2[c];
        float4 x3 = f3[c];
        float4 b = swt[c];
        a0 += x0.x * b.x + x0.y * b.y + x0.z * b.z + x0.w * b.w;
        a1 += x1.x * b.x + x1.y * b.y + x1.z * b.z + x1.w * b.w;
        a2 += x2.x * b.x + x2.y * b.y + x2.z * b.z + x2.w * b.w;
        a3 += x3.x * b.x + x3.y * b.y + x3.z * b.z + x3.w * b.w;
    }
#pragma unroll
    for (int o = 16; o > 0; o >>= 1) {
        a0 += __shfl_down_sync(0xffffffffu, a0, o);
        a1 += __shfl_down_sync(0xffffffffu, a1, o);
        a2 += __shfl_down_sync(0xffffffffu, a2, o);
        a3 += __shfl_down_sync(0xffffffffu, a3, o);
    }
    if (lane == 0) {
        g_h[row0]     = a0 * g_norm[row0];
        g_h[row0 + 1] = a1 * g_norm[row0 + 1];
        g_h[row0 + 2] = a2 * g_norm[row0 + 2];
        g_h[row0 + 3] = a3 * g_norm[row0 + 3];
    }
}

// ---------------------------------------------------------------------------
// Agg partials: PPARTS CTAs per graph. h staged in shared, shared float
// accumulator, plain stores of partials.
// ---------------------------------------------------------------------------
__global__ void k_agg_part(const void* __restrict__ src,
                           const void* __restrict__ dst, long long EPG,
                           int EPP, int use16, long long E) {
    __shared__ float sh[NPG];
    __shared__ float sacc[NPG];
    __shared__ int s_is64;
    int g = blockIdx.x >> 4;
    int p = blockIdx.x & (PPARTS - 1);
    int hb = g * NPG;
    if (threadIdx.x == 0) s_is64 = probe_is64(src, E);
    for (int j = threadIdx.x; j < NPG; j += blockDim.x) {
        sh[j] = g_h[hb + j];
        sacc[j] = 0.f;
    }
    __syncthreads();

    const int is64 = s_is64;
    long long base = (long long)g * EPG + (long long)p * EPP;
    long long rem = EPG - (long long)p * EPP;
    int cnt = (rem < (long long)EPP) ? (rem > 0 ? (int)rem : 0) : EPP;

    for (int e = threadIdx.x; e < cnt; e += blockDim.x) {
        long long idx = base + e;
        int s = edge_idx(src, idx, is64) & (NPG - 1);
        int d = use16 ? (int)g_dst16[idx]
                      : (edge_idx(dst, idx, is64) & (NPG - 1));
        atomicAdd(&sacc[d], sh[s]);
    }
    __syncthreads();

    int out = p * NTOT + g * NPG;
    for (int j = threadIdx.x; j < NPG; j += blockDim.x)
        g_pagg[out + j] = sacc[j];
}

// ---------------------------------------------------------------------------
// Fused: w = relu((sum agg partials)*norm + bias); stable rank
// (rank[i] = #{w_j<w_i} + #{j<i: w_j==w_i}, matches argsort(argsort));
// wb = (rank >= DROPN) ? w : 0.  One 1024-thread CTA per graph.
// ---------------------------------------------------------------------------
__global__ void k_rank(const float* __restrict__ bias) {
    __shared__ float sw[NPG];
    int g = blockIdx.x;
    int base = g * NPG;
    int i = threadIdx.x;             // blockDim.x == NPG

    float s = 0.f;
#pragma unroll
    for (int p = 0; p < PPARTS; p++) s += g_pagg[p * NTOT + base + i];
    float v = s * g_norm[base + i] + bias[0];
    float wi = v > 0.f ? v : 0.f;
    sw[i] = wi;
    __syncthreads();

    int cnt = 0;
    const float4* sw4 = (const float4*)sw;
#pragma unroll 4
    for (int jb = 0; jb < NPG / 4; ++jb) {
        float4 q = sw4[jb];
        int j = jb * 4;
        cnt += (int)(q.x < wi) + (int)(q.y < wi) + (int)(q.z < wi) + (int)(q.w < wi);
        cnt += (int)((q.x == wi) & (j + 0 < i));
        cnt += (int)((q.y == wi) & (j + 1 < i));
        cnt += (int)((q.z == wi) & (j + 2 < i));
        cnt += (int)((q.w == wi) & (j + 3 < i));
    }
    g_wb[base + i] = (cnt >= DROPN) ? wi : 0.f;
}

// ---------------------------------------------------------------------------
// out[n,:] = features[n,:] * wb[n].  4 rows per 256-thread CTA, 2 independent
// float4 ops per thread; zero rows skip the feature read.
// ---------------------------------------------------------------------------
__global__ void k_gate(const float* __restrict__ feat,
                       float* __restrict__ out) {
    int row = blockIdx.x * 4 + (threadIdx.x >> 6);
    int col = threadIdx.x & 63;
    float wv = g_wb[row];
    const float4* fi = (const float4*)(feat + (long long)row * DIM);
    float4* fo = (float4*)(out + (long long)row * DIM);
    if (wv == 0.f) {
        float4 z = make_float4(0.f, 0.f, 0.f, 0.f);
        fo[col] = z;
        fo[col + 64] = z;
    } else {
        float4 a = fi[col];
        float4 b = fi[col + 64];
        fo[col]      = make_float4(a.x * wv, a.y * wv, a.z * wv, a.w * wv);
        fo[col + 64] = make_float4(b.x * wv, b.y * wv, b.z * wv, b.w * wv);
    }
}

// ---------------------------------------------------------------------------
extern "C" void kernel_launch(void* const* d_in, const int* in_sizes, int n_in,
                              void* d_out, int out_size) {
    const float* feat   = (const float*)d_in[0];
    const void*  src    = d_in[1];
    const void*  dst    = d_in[2];
    const float* weight = (const float*)d_in[3];
    const float* bias   = (const float*)d_in[4];
    long long E = (long long)in_sizes[1];
    long long EPG = E / BGRAPHS;
    int EPP = (int)((EPG + PPARTS - 1) / PPARTS);
    int use16 = (E <= (long long)ECAP) ? 1 : 0;

    k_deg_part<<<BGRAPHS * PPARTS, 256>>>(dst, EPG, EPP, use16, E);
    k_norm<<<NTOT / 256, 256>>>();

    k_h<<<NTOT / 64, 512>>>(feat, weight);   // 16 warps/CTA, 4 rows/warp

    k_agg_part<<<BGRAPHS * PPARTS, 256>>>(src, dst, EPG, EPP, use16, E);

    k_rank<<<BGRAPHS, NPG>>>(bias);

    k_gate<<<NTOT / 4, 256>>>(feat, (float*)d_out);
}

// round 6
// speedup vs baseline: 1.0042x; 1.0042x over previous
#include <cuda_runtime.h>

#define BGRAPHS 64
#define NPG     1024
#define NTOT    (BGRAPHS * NPG)   // 65536
#define DIM     512
#define DROPN   512               // NPG - ceil(0.5*NPG)
#define PPARTS  16                // partial copies per graph (privatized reduce)
#define ECAP    (64 * 1024 * 32)  // dst16 cache capacity (expected E)

// ---- scratch (device globals: no allocation allowed) ----
__device__ float g_h[NTOT];
__device__ float g_norm[NTOT];
__device__ float g_wb[NTOT];
__device__ int   g_pdeg[PPARTS * NTOT];          // 4 MB partial degree hist
__device__ float g_pagg[PPARTS * NTOT];          // 4 MB partial agg sums
__device__ unsigned short g_dst16[ECAP];         // 4 MB compacted local dst
__device__ int   g_is64;

// ---------------------------------------------------------------------------
// int64-vs-int32 probe (separate tiny kernel — inline version regressed R5).
// Node indices < 2^17, so for int64 data every odd 32-bit word is zero.
// ---------------------------------------------------------------------------
__global__ void k_probe(const unsigned* __restrict__ w, int nwords_min) {
    int i = 1 + 2 * threadIdx.x;            // odd words, 32 lanes in parallel
    unsigned v = (i < nwords_min) ? w[i] : 0u;
    unsigned any = __ballot_sync(0xffffffffu, v != 0u);
    if (threadIdx.x == 0) g_is64 = any ? 0 : 1;
}

__device__ __forceinline__ int edge_idx(const void* p, long long e, int is64) {
    if (is64) return (int)((const long long*)p)[e];
    return ((const int*)p)[e];
}

// ---------------------------------------------------------------------------
// Degree partials: PPARTS CTAs per graph, shared int histogram, plain stores.
// Edge loop unrolled x4 for index-load MLP. Also compacts dst to uint16.
// ---------------------------------------------------------------------------
__global__ void k_deg_part(const void* __restrict__ dst, long long EPG,
                           int EPP, int use16) {
    __shared__ int sacc[NPG];
    int g = blockIdx.x >> 4;
    int p = blockIdx.x & (PPARTS - 1);
    for (int j = threadIdx.x; j < NPG; j += blockDim.x) sacc[j] = 0;
    __syncthreads();

    const int is64 = g_is64;
    long long base = (long long)g * EPG + (long long)p * EPP;
    long long rem = EPG - (long long)p * EPP;
    int cnt = (rem < (long long)EPP) ? (rem > 0 ? (int)rem : 0) : EPP;
    const int BS = 256;

    int e = threadIdx.x;
    for (; e + 3 * BS < cnt; e += 4 * BS) {
        int d0 = edge_idx(dst, base + e,          is64) & (NPG - 1);
        int d1 = edge_idx(dst, base + e + BS,     is64) & (NPG - 1);
        int d2 = edge_idx(dst, base + e + 2 * BS, is64) & (NPG - 1);
        int d3 = edge_idx(dst, base + e + 3 * BS, is64) & (NPG - 1);
        atomicAdd(&sacc[d0], 1);
        atomicAdd(&sacc[d1], 1);
        atomicAdd(&sacc[d2], 1);
        atomicAdd(&sacc[d3], 1);
        if (use16) {
            g_dst16[base + e]          = (unsigned short)d0;
            g_dst16[base + e + BS]     = (unsigned short)d1;
            g_dst16[base + e + 2 * BS] = (unsigned short)d2;
            g_dst16[base + e + 3 * BS] = (unsigned short)d3;
        }
    }
    for (; e < cnt; e += BS) {
        int d = edge_idx(dst, base + e, is64) & (NPG - 1);
        atomicAdd(&sacc[d], 1);
        if (use16) g_dst16[base + e] = (unsigned short)d;
    }
    __syncthreads();

    int out = p * NTOT + g * NPG;
    for (int j = threadIdx.x; j < NPG; j += blockDim.x)
        g_pdeg[out + j] = sacc[j];
}

// ---------------------------------------------------------------------------
// norm[i] = deg^-0.5 (0 if isolated); deg = sum of 16 partials
// ---------------------------------------------------------------------------
__global__ void k_norm() {
    int i = blockIdx.x * blockDim.x + threadIdx.x;
    if (i >= NTOT) return;
    int c = 0;
#pragma unroll
    for (int p = 0; p < PPARTS; p++) c += g_pdeg[p * NTOT + i];
    g_norm[i] = (c > 0) ? rsqrtf((float)c) : 0.0f;
}

// ---------------------------------------------------------------------------
// h[n] = dot(features[n,:], weight) * norm[n].  Two rows per warp
// (measured best: 24.9us @ DRAM 70%; 4 rows regressed via occupancy).
// ---------------------------------------------------------------------------
__global__ void k_h(const float* __restrict__ feat,
                    const float* __restrict__ weight) {
    __shared__ float4 swt[DIM / 4];
    int t = threadIdx.x;
    if (t < DIM / 4) swt[t] = ((const float4*)weight)[t];
    __syncthreads();

    int warp = t >> 5, lane = t & 31;
    int row0 = (blockIdx.x * (blockDim.x >> 5) + warp) * 2;
    if (row0 >= NTOT) return;

    const float4* f0 = (const float4*)(feat + (long long)row0 * DIM);
    const float4* f1 = f0 + DIM / 4;
    float a0 = 0.f, a1 = 0.f;
#pragma unroll
    for (int k = 0; k < 4; k++) {
        float4 x = f0[lane + 32 * k];
        float4 y = f1[lane + 32 * k];
        float4 b = swt[lane + 32 * k];
        a0 += x.x * b.x + x.y * b.y + x.z * b.z + x.w * b.w;
        a1 += y.x * b.x + y.y * b.y + y.z * b.z + y.w * b.w;
    }
#pragma unroll
    for (int o = 16; o > 0; o >>= 1) {
        a0 += __shfl_down_sync(0xffffffffu, a0, o);
        a1 += __shfl_down_sync(0xffffffffu, a1, o);
    }
    if (lane == 0) {
        g_h[row0]     = a0 * g_norm[row0];
        g_h[row0 + 1] = a1 * g_norm[row0 + 1];
    }
}

// ---------------------------------------------------------------------------
// Agg partials: PPARTS CTAs per graph. h staged in shared, shared float
// accumulator, plain stores. Edge loop unrolled x4 for index-load MLP.
// ---------------------------------------------------------------------------
__global__ void k_agg_part(const void* __restrict__ src,
                           const void* __restrict__ dst, long long EPG,
                           int EPP, int use16) {
    __shared__ float sh[NPG];
    __shared__ float sacc[NPG];
    int g = blockIdx.x >> 4;
    int p = blockIdx.x & (PPARTS - 1);
    int hb = g * NPG;
    for (int j = threadIdx.x; j < NPG; j += blockDim.x) {
        sh[j] = g_h[hb + j];
        sacc[j] = 0.f;
    }
    __syncthreads();

    const int is64 = g_is64;
    long long base = (long long)g * EPG + (long long)p * EPP;
    long long rem = EPG - (long long)p * EPP;
    int cnt = (rem < (long long)EPP) ? (rem > 0 ? (int)rem : 0) : EPP;
    const int BS = 256;

    int e = threadIdx.x;
    for (; e + 3 * BS < cnt; e += 4 * BS) {
        int s0 = edge_idx(src, base + e,          is64) & (NPG - 1);
        int s1 = edge_idx(src, base + e + BS,     is64) & (NPG - 1);
        int s2 = edge_idx(src, base + e + 2 * BS, is64) & (NPG - 1);
        int s3 = edge_idx(src, base + e + 3 * BS, is64) & (NPG - 1);
        int d0, d1, d2, d3;
        if (use16) {
            d0 = (int)g_dst16[base + e];
            d1 = (int)g_dst16[base + e + BS];
            d2 = (int)g_dst16[base + e + 2 * BS];
            d3 = (int)g_dst16[base + e + 3 * BS];
        } else {
            d0 = edge_idx(dst, base + e,          is64) & (NPG - 1);
            d1 = edge_idx(dst, base + e + BS,     is64) & (NPG - 1);
            d2 = edge_idx(dst, base + e + 2 * BS, is64) & (NPG - 1);
            d3 = edge_idx(dst, base + e + 3 * BS, is64) & (NPG - 1);
        }
        atomicAdd(&sacc[d0], sh[s0]);
        atomicAdd(&sacc[d1], sh[s1]);
        atomicAdd(&sacc[d2], sh[s2]);
        atomicAdd(&sacc[d3], sh[s3]);
    }
    for (; e < cnt; e += BS) {
        int s = edge_idx(src, base + e, is64) & (NPG - 1);
        int d = use16 ? (int)g_dst16[base + e]
                      : (edge_idx(dst, base + e, is64) & (NPG - 1));
        atomicAdd(&sacc[d], sh[s]);
    }
    __syncthreads();

    int out = p * NTOT + g * NPG;
    for (int j = threadIdx.x; j < NPG; j += blockDim.x)
        g_pagg[out + j] = sacc[j];
}

// ---------------------------------------------------------------------------
// Fused: w = relu((sum agg partials)*norm + bias); stable rank
// (rank[i] = #{w_j<w_i} + #{j<i: w_j==w_i}, matches argsort(argsort));
// wb = (rank >= DROPN) ? w : 0.  One 1024-thread CTA per graph.
// ---------------------------------------------------------------------------
__global__ void k_rank(const float* __restrict__ bias) {
    __shared__ float sw[NPG];
    int g = blockIdx.x;
    int base = g * NPG;
    int i = threadIdx.x;             // blockDim.x == NPG

    float s = 0.f;
#pragma unroll
    for (int p = 0; p < PPARTS; p++) s += g_pagg[p * NTOT + base + i];
    float v = s * g_norm[base + i] + bias[0];
    float wi = v > 0.f ? v : 0.f;
    sw[i] = wi;
    __syncthreads();

    int cnt = 0;
    const float4* sw4 = (const float4*)sw;
#pragma unroll 4
    for (int jb = 0; jb < NPG / 4; ++jb) {
        float4 q = sw4[jb];
        int j = jb * 4;
        cnt += (int)(q.x < wi) + (int)(q.y < wi) + (int)(q.z < wi) + (int)(q.w < wi);
        cnt += (int)((q.x == wi) & (j + 0 < i));
        cnt += (int)((q.y == wi) & (j + 1 < i));
        cnt += (int)((q.z == wi) & (j + 2 < i));
        cnt += (int)((q.w == wi) & (j + 3 < i));
    }
    g_wb[base + i] = (cnt >= DROPN) ? wi : 0.f;
}

// ---------------------------------------------------------------------------
// out[n,:] = features[n,:] * wb[n].  2 rows per 256-thread CTA (measured-good
// form); zero rows skip the feature read.
// ---------------------------------------------------------------------------
__global__ void k_gate(const float* __restrict__ feat,
                       float* __restrict__ out) {
    int row = blockIdx.x * 2 + (threadIdx.x >> 7);
    int col = threadIdx.x & 127;
    float wv = g_wb[row];
    const float4* fi = (const float4*)(feat + (long long)row * DIM);
    float4* fo = (float4*)(out + (long long)row * DIM);
    float4 r;
    if (wv == 0.f) {
        r = make_float4(0.f, 0.f, 0.f, 0.f);
    } else {
        float4 a = fi[col];
        r = make_float4(a.x * wv, a.y * wv, a.z * wv, a.w * wv);
    }
    fo[col] = r;
}

// ---------------------------------------------------------------------------
extern "C" void kernel_launch(void* const* d_in, const int* in_sizes, int n_in,
                              void* d_out, int out_size) {
    const float* feat   = (const float*)d_in[0];
    const void*  src    = d_in[1];
    const void*  dst    = d_in[2];
    const float* weight = (const float*)d_in[3];
    const float* bias   = (const float*)d_in[4];
    long long E = (long long)in_sizes[1];
    long long EPG = E / BGRAPHS;
    int EPP = (int)((EPG + PPARTS - 1) / PPARTS);
    int use16 = (E <= (long long)ECAP) ? 1 : 0;

    k_probe<<<1, 32>>>((const unsigned*)src, (int)E);

    k_deg_part<<<BGRAPHS * PPARTS, 256>>>(dst, EPG, EPP, use16);
    k_norm<<<NTOT / 256, 256>>>();

    k_h<<<NTOT / 32, 512>>>(feat, weight);   // 16 warps/CTA, 2 rows/warp

    k_agg_part<<<BGRAPHS * PPARTS, 256>>>(src, dst, EPG, EPP, use16);

    k_rank<<<BGRAPHS, NPG>>>(bias);

    k_gate<<<NTOT / 2, 256>>>(feat, (float*)d_out);
}

// round 9
// speedup vs baseline: 1.4117x; 1.4058x over previous
#include <cuda_runtime.h>

#define BGRAPHS 64
#define NPG     1024
#define NTOT    (BGRAPHS * NPG)   // 65536
#define DIM     512
#define DROPN   512               // NPG - ceil(0.5*NPG)
#define PPARTS  16                // partial copies per graph (privatized reduce)
#define ECAP    (64 * 1024 * 32)  // dst16 cache capacity (expected E)

// ---- scratch (device globals: no allocation allowed) ----
__device__ float g_h[NTOT];
__device__ float g_norm[NTOT];
__device__ float g_wb[NTOT];
__device__ int   g_pdeg[PPARTS * NTOT];          // 4 MB partial degree hist
__device__ float g_pagg[PPARTS * NTOT];          // 4 MB partial agg sums
__device__ unsigned short g_dst16[ECAP];         // 4 MB compacted local dst
__device__ int   g_is64;

// ---------------------------------------------------------------------------
// int64-vs-int32 probe. Node indices < 2^17, so int64 data has all odd
// 32-bit words zero.
// ---------------------------------------------------------------------------
__global__ void k_probe(const unsigned* __restrict__ w, int nwords_min) {
    int i = 1 + 2 * threadIdx.x;
    unsigned v = (i < nwords_min) ? w[i] : 0u;
    unsigned any = __ballot_sync(0xffffffffu, v != 0u);
    if (threadIdx.x == 0) g_is64 = any ? 0 : 1;
}

__device__ __forceinline__ int edge_idx(const void* p, long long e, int is64) {
    if (is64) return (int)((const long long*)p)[e];
    return ((const int*)p)[e];
}

// ---------------------------------------------------------------------------
// Degree partials: PPARTS CTAs per graph, shared int histogram, plain stores.
// Edge loop unrolled x4 for index-load MLP. Also compacts dst to uint16.
// ---------------------------------------------------------------------------
__global__ void k_deg_part(const void* __restrict__ dst, long long EPG,
                           int EPP, int use16) {
    __shared__ int sacc[NPG];
    int g = blockIdx.x >> 4;
    int p = blockIdx.x & (PPARTS - 1);
    for (int j = threadIdx.x; j < NPG; j += blockDim.x) sacc[j] = 0;
    __syncthreads();

    const int is64 = g_is64;
    long long base = (long long)g * EPG + (long long)p * EPP;
    long long rem = EPG - (long long)p * EPP;
    int cnt = (rem < (long long)EPP) ? (rem > 0 ? (int)rem : 0) : EPP;
    const int BS = 256;

    int e = threadIdx.x;
    for (; e + 3 * BS < cnt; e += 4 * BS) {
        int d0 = edge_idx(dst, base + e,          is64) & (NPG - 1);
        int d1 = edge_idx(dst, base + e + BS,     is64) & (NPG - 1);
        int d2 = edge_idx(dst, base + e + 2 * BS, is64) & (NPG - 1);
        int d3 = edge_idx(dst, base + e + 3 * BS, is64) & (NPG - 1);
        atomicAdd(&sacc[d0], 1);
        atomicAdd(&sacc[d1], 1);
        atomicAdd(&sacc[d2], 1);
        atomicAdd(&sacc[d3], 1);
        if (use16) {
            g_dst16[base + e]          = (unsigned short)d0;
            g_dst16[base + e + BS]     = (unsigned short)d1;
            g_dst16[base + e + 2 * BS] = (unsigned short)d2;
            g_dst16[base + e + 3 * BS] = (unsigned short)d3;
        }
    }
    for (; e < cnt; e += BS) {
        int d = edge_idx(dst, base + e, is64) & (NPG - 1);
        atomicAdd(&sacc[d], 1);
        if (use16) g_dst16[base + e] = (unsigned short)d;
    }
    __syncthreads();

    int out = p * NTOT + g * NPG;
    for (int j = threadIdx.x; j < NPG; j += blockDim.x)
        g_pdeg[out + j] = sacc[j];
}

// ---------------------------------------------------------------------------
// norm[i] = deg^-0.5 (0 if isolated); deg = sum of 16 partials
// ---------------------------------------------------------------------------
__global__ void k_norm() {
    int i = blockIdx.x * blockDim.x + threadIdx.x;
    if (i >= NTOT) return;
    int c = 0;
#pragma unroll
    for (int p = 0; p < PPARTS; p++) c += g_pdeg[p * NTOT + i];
    g_norm[i] = (c > 0) ? rsqrtf((float)c) : 0.0f;
}

// ---------------------------------------------------------------------------
// h[n] = dot(features[n,:], weight) * norm[n].  Two rows per warp, 256-thread
// CTAs for finer SM packing (8 warps/CTA).
// ---------------------------------------------------------------------------
__global__ void k_h(const float* __restrict__ feat,
                    const float* __restrict__ weight) {
    __shared__ float4 swt[DIM / 4];
    int t = threadIdx.x;
    if (t < DIM / 4) swt[t] = ((const float4*)weight)[t];
    __syncthreads();

    int warp = t >> 5, lane = t & 31;
    int row0 = (blockIdx.x * (blockDim.x >> 5) + warp) * 2;
    if (row0 >= NTOT) return;

    const float4* f0 = (const float4*)(feat + (long long)row0 * DIM);
    const float4* f1 = f0 + DIM / 4;
    float a0 = 0.f, a1 = 0.f;
#pragma unroll
    for (int k = 0; k < 4; k++) {
        float4 x = f0[lane + 32 * k];
        float4 y = f1[lane + 32 * k];
        float4 b = swt[lane + 32 * k];
        a0 += x.x * b.x + x.y * b.y + x.z * b.z + x.w * b.w;
        a1 += y.x * b.x + y.y * b.y + y.z * b.z + y.w * b.w;
    }
#pragma unroll
    for (int o = 16; o > 0; o >>= 1) {
        a0 += __shfl_down_sync(0xffffffffu, a0, o);
        a1 += __shfl_down_sync(0xffffffffu, a1, o);
    }
    if (lane == 0) {
        g_h[row0]     = a0 * g_norm[row0];
        g_h[row0 + 1] = a1 * g_norm[row0 + 1];
    }
}

// ---------------------------------------------------------------------------
// Agg partials: PPARTS CTAs per graph. h staged in shared, shared float
// accumulator, plain stores. Edge loop unrolled x4 for index-load MLP.
// ---------------------------------------------------------------------------
__global__ void k_agg_part(const void* __restrict__ src,
                           const void* __restrict__ dst, long long EPG,
                           int EPP, int use16) {
    __shared__ float sh[NPG];
    __shared__ float sacc[NPG];
    int g = blockIdx.x >> 4;
    int p = blockIdx.x & (PPARTS - 1);
    int hb = g * NPG;
    for (int j = threadIdx.x; j < NPG; j += blockDim.x) {
        sh[j] = g_h[hb + j];
        sacc[j] = 0.f;
    }
    __syncthreads();

    const int is64 = g_is64;
    long long base = (long long)g * EPG + (long long)p * EPP;
    long long rem = EPG - (long long)p * EPP;
    int cnt = (rem < (long long)EPP) ? (rem > 0 ? (int)rem : 0) : EPP;
    const int BS = 256;

    int e = threadIdx.x;
    for (; e + 3 * BS < cnt; e += 4 * BS) {
        int s0 = edge_idx(src, base + e,          is64) & (NPG - 1);
        int s1 = edge_idx(src, base + e + BS,     is64) & (NPG - 1);
        int s2 = edge_idx(src, base + e + 2 * BS, is64) & (NPG - 1);
        int s3 = edge_idx(src, base + e + 3 * BS, is64) & (NPG - 1);
        int d0, d1, d2, d3;
        if (use16) {
            d0 = (int)g_dst16[base + e];
            d1 = (int)g_dst16[base + e + BS];
            d2 = (int)g_dst16[base + e + 2 * BS];
            d3 = (int)g_dst16[base + e + 3 * BS];
        } else {
            d0 = edge_idx(dst, base + e,          is64) & (NPG - 1);
            d1 = edge_idx(dst, base + e + BS,     is64) & (NPG - 1);
            d2 = edge_idx(dst, base + e + 2 * BS, is64) & (NPG - 1);
            d3 = edge_idx(dst, base + e + 3 * BS, is64) & (NPG - 1);
        }
        atomicAdd(&sacc[d0], sh[s0]);
        atomicAdd(&sacc[d1], sh[s1]);
        atomicAdd(&sacc[d2], sh[s2]);
        atomicAdd(&sacc[d3], sh[s3]);
    }
    for (; e < cnt; e += BS) {
        int s = edge_idx(src, base + e, is64) & (NPG - 1);
        int d = use16 ? (int)g_dst16[base + e]
                      : (edge_idx(dst, base + e, is64) & (NPG - 1));
        atomicAdd(&sacc[d], sh[s]);
    }
    __syncthreads();

    int out = p * NTOT + g * NPG;
    for (int j = threadIdx.x; j < NPG; j += blockDim.x)
        g_pagg[out + j] = sacc[j];
}

// ---------------------------------------------------------------------------
// Fused w + select-based top-k mask. One 1024-thread CTA per graph.
//   w_i = relu((sum agg partials)*norm + bias)
//   key = float bits (nonneg floats order as uint32)
//   T   = key at stable-sort position DROPN-1 (4-pass MSD radix select)
//   keep iff  key>T  or  (key==T and #{j<i: key_j==T} >= DROPN - #{key<T})
// Identical to rank_i = #{w_j<w_i}+#{j<i: w_j==w_i} >= DROPN (argsort(argsort)).
// ---------------------------------------------------------------------------
__global__ void k_rank(const float* __restrict__ bias) {
    __shared__ unsigned skey[NPG];
    __shared__ int sbin[256];
    __shared__ int s_sel[2];       // [0]=prefix, [1]=remaining rank r
    __shared__ int s_wsum[32];
    __shared__ int s_nless;

    int g = blockIdx.x;
    int base = g * NPG;
    int i = threadIdx.x;           // blockDim.x == NPG == 1024
    int wid = i >> 5, lane = i & 31;

    float s = 0.f;
#pragma unroll
    for (int p = 0; p < PPARTS; p++) s += g_pagg[p * NTOT + base + i];
    float v = s * g_norm[base + i] + bias[0];
    float w = v > 0.f ? v : 0.f;
    unsigned key = __float_as_uint(w);
    skey[i] = key;
    if (i == 0) { s_sel[0] = 0; s_sel[1] = DROPN - 1; s_nless = 0; }
    __syncthreads();

    // ---- 4-pass MSD radix select for key at sorted rank DROPN-1 ----
#pragma unroll
    for (int pass = 3; pass >= 0; pass--) {
        int shift = pass * 8;
        if (i < 256) sbin[i] = 0;
        __syncthreads();
        unsigned prefix = (unsigned)s_sel[0];
        bool match = (pass == 3) || ((key >> (shift + 8)) == prefix);
        if (match) atomicAdd(&sbin[(key >> shift) & 255], 1);
        __syncthreads();
        if (i < 32) {               // warp 0 scans 256 bins
            int r = s_sel[1];
            int loc[8], lsum = 0;
#pragma unroll
            for (int t = 0; t < 8; t++) { loc[t] = sbin[i * 8 + t]; lsum += loc[t]; }
            int incl = lsum;
#pragma unroll
            for (int o = 1; o < 32; o <<= 1) {
                int y = __shfl_up_sync(0xffffffffu, incl, o);
                if (lane >= o) incl += y;
            }
            int excl = incl - lsum;
            bool has = (excl <= r) && (r < incl);
            if (has) {
                int rr = r - excl;
                int b = 0;
#pragma unroll
                for (int t = 0; t < 8; t++) {
                    if (rr >= loc[t] && b == t) { rr -= loc[t]; b = t + 1; }
                }
                int binfull = i * 8 + b;
                s_sel[0] = (pass == 3) ? binfull : (int)((prefix << 8) | (unsigned)binfull);
                s_sel[1] = rr;
            }
        }
        __syncthreads();
    }

    unsigned T = (unsigned)s_sel[0];

    // ---- nLess and stable position among ties ----
    unsigned lm = __ballot_sync(0xffffffffu, key < T);
    unsigned em = __ballot_sync(0xffffffffu, key == T);
    if (lane == 0) {
        atomicAdd(&s_nless, __popc(lm));
        s_wsum[wid] = __popc(em);
    }
    __syncthreads();
    if (i < 32) {                   // exclusive scan of per-warp tie counts
        int x = s_wsum[i];
        int incl = x;
#pragma unroll
        for (int o = 1; o < 32; o <<= 1) {
            int y = __shfl_up_sync(0xffffffffu, incl, o);
            if (lane >= o) incl += y;
        }
        s_wsum[i] = incl - x;
    }
    __syncthreads();

    int pos = s_wsum[wid] + __popc(em & ((1u << lane) - 1u));
    int needEq = DROPN - s_nless;
    bool keep = (key > T) || ((key == T) && (pos >= needEq));
    g_wb[base + i] = keep ? w : 0.f;
}

// ---------------------------------------------------------------------------
// out[n,:] = features[n,:] * wb[n].  2 rows per 256-thread CTA (measured-good
// form); zero rows skip the feature read.
// ---------------------------------------------------------------------------
__global__ void k_gate(const float* __restrict__ feat,
                       float* __restrict__ out) {
    int row = blockIdx.x * 2 + (threadIdx.x >> 7);
    int col = threadIdx.x & 127;
    float wv = g_wb[row];
    const float4* fi = (const float4*)(feat + (long long)row * DIM);
    float4* fo = (float4*)(out + (long long)row * DIM);
    float4 r;
    if (wv == 0.f) {
        r = make_float4(0.f, 0.f, 0.f, 0.f);
    } else {
        float4 a = fi[col];
        r = make_float4(a.x * wv, a.y * wv, a.z * wv, a.w * wv);
    }
    fo[col] = r;
}

// ---------------------------------------------------------------------------
extern "C" void kernel_launch(void* const* d_in, const int* in_sizes, int n_in,
                              void* d_out, int out_size) {
    const float* feat   = (const float*)d_in[0];
    const void*  src    = d_in[1];
    const void*  dst    = d_in[2];
    const float* weight = (const float*)d_in[3];
    const float* bias   = (const float*)d_in[4];
    long long E = (long long)in_sizes[1];
    long long EPG = E / BGRAPHS;
    int EPP = (int)((EPG + PPARTS - 1) / PPARTS);
    int use16 = (E <= (long long)ECAP) ? 1 : 0;

    k_probe<<<1, 32>>>((const unsigned*)src, (int)E);

    k_deg_part<<<BGRAPHS * PPARTS, 256>>>(dst, EPG, EPP, use16);
    k_norm<<<NTOT / 256, 256>>>();

    k_h<<<NTOT / 16, 256>>>(feat, weight);   // 8 warps/CTA, 2 rows/warp

    k_agg_part<<<BGRAPHS * PPARTS, 256>>>(src, dst, EPG, EPP, use16);

    k_rank<<<BGRAPHS, NPG>>>(bias);

    k_gate<<<NTOT / 2, 256>>>(feat, (float*)d_out);
}

// round 10
// speedup vs baseline: 1.6009x; 1.1340x over previous
#include <cuda_runtime.h>

#define BGRAPHS 64
#define NPG     1024
#define NTOT    (BGRAPHS * NPG)   // 65536
#define DIM     512
#define DROPN   512               // NPG - ceil(0.5*NPG)
#define PPARTS  16                // partial copies per graph (privatized reduce)
#define ECAP    (64 * 1024 * 32)  // dst16 cache capacity (expected E)

// ---- scratch (device globals: no allocation allowed) ----
__device__ float g_h[NTOT];
__device__ float g_norm[NTOT];
__device__ float g_wb[NTOT];
__device__ int   g_pdeg[PPARTS * NTOT];          // 4 MB partial degree hist
__device__ float g_pagg[PPARTS * NTOT];          // 4 MB partial agg sums
__device__ unsigned short g_dst16[ECAP];         // 4 MB compacted local dst

// ---------------------------------------------------------------------------
// Warp-parallel int64-vs-int32 probe (warp 0 of a CTA): node indices < 2^17,
// so int64 data has all odd 32-bit words zero. 32 concurrent loads, one
// round trip — NOT the serial per-CTA loop that regressed R5.
// Caller: threads 0..31 execute, result returned in all 32 lanes.
// ---------------------------------------------------------------------------
__device__ __forceinline__ int warp_probe_is64(const void* p, long long nelem) {
    const unsigned* w = (const unsigned*)p;
    int lane = threadIdx.x & 31;
    int i = 1 + 2 * lane;
    unsigned v = ((long long)i < nelem * 2) ? w[i] : 0u;
    unsigned any = __ballot_sync(0xffffffffu, v != 0u);
    return any ? 0 : 1;
}

__device__ __forceinline__ int edge_idx(const void* p, long long e, int is64) {
    if (is64) return (int)((const long long*)p)[e];
    return ((const int*)p)[e];
}

// ---------------------------------------------------------------------------
// Degree partials: PPARTS CTAs per graph, shared int histogram, plain stores.
// Vectorized: 8 edges per thread per iteration. Compacts dst to uint16.
// ---------------------------------------------------------------------------
__global__ void k_deg_part(const void* __restrict__ dst, long long EPG,
                           int EPP, int use16, long long E) {
    __shared__ int sacc[NPG];
    __shared__ int s_is64;
    int g = blockIdx.x >> 4;
    int p = blockIdx.x & (PPARTS - 1);
    if (threadIdx.x < 32) {
        int r = warp_probe_is64(dst, E);
        if (threadIdx.x == 0) s_is64 = r;
    }
    for (int j = threadIdx.x; j < NPG; j += blockDim.x) sacc[j] = 0;
    __syncthreads();

    const int is64 = s_is64;
    long long base = (long long)g * EPG + (long long)p * EPP;   // multiple of EPP
    long long rem = EPG - (long long)p * EPP;
    int cnt = (rem < (long long)EPP) ? (rem > 0 ? (int)rem : 0) : EPP;
    const int BS = 256;
    int t = threadIdx.x;
    int nfull = cnt >> 3;                  // groups of 8 consecutive edges

    for (int gi = t; gi < nfull; gi += BS) {
        long long e0 = base + ((long long)gi << 3);
        int d[8];
        if (is64) {
            const longlong4* q = (const longlong4*)((const long long*)dst + e0);
            longlong4 a = q[0], b = q[1];
            d[0] = (int)a.x & (NPG - 1); d[1] = (int)a.y & (NPG - 1);
            d[2] = (int)a.z & (NPG - 1); d[3] = (int)a.w & (NPG - 1);
            d[4] = (int)b.x & (NPG - 1); d[5] = (int)b.y & (NPG - 1);
            d[6] = (int)b.z & (NPG - 1); d[7] = (int)b.w & (NPG - 1);
        } else {
            const int4* q = (const int4*)((const int*)dst + e0);
            int4 a = q[0], b = q[1];
            d[0] = a.x & (NPG - 1); d[1] = a.y & (NPG - 1);
            d[2] = a.z & (NPG - 1); d[3] = a.w & (NPG - 1);
            d[4] = b.x & (NPG - 1); d[5] = b.y & (NPG - 1);
            d[6] = b.z & (NPG - 1); d[7] = b.w & (NPG - 1);
        }
#pragma unroll
        for (int k = 0; k < 8; k++) atomicAdd(&sacc[d[k]], 1);
        if (use16) {
            uint4 s;
            s.x = (unsigned)d[0] | ((unsigned)d[1] << 16);
            s.y = (unsigned)d[2] | ((unsigned)d[3] << 16);
            s.z = (unsigned)d[4] | ((unsigned)d[5] << 16);
            s.w = (unsigned)d[6] | ((unsigned)d[7] << 16);
            *(uint4*)(g_dst16 + e0) = s;
        }
    }
    for (int e = (nfull << 3) + t; e < cnt; e += BS) {           // tail
        int d = edge_idx(dst, base + e, is64) & (NPG - 1);
        atomicAdd(&sacc[d], 1);
        if (use16) g_dst16[base + e] = (unsigned short)d;
    }
    __syncthreads();

    int out = p * NTOT + g * NPG;
    for (int j = threadIdx.x; j < NPG; j += blockDim.x)
        g_pdeg[out + j] = sacc[j];
}

// ---------------------------------------------------------------------------
// norm[i] = deg^-0.5 (0 if isolated); deg = sum of 16 partials
// ---------------------------------------------------------------------------
__global__ void k_norm() {
    int i = blockIdx.x * blockDim.x + threadIdx.x;
    if (i >= NTOT) return;
    int c = 0;
#pragma unroll
    for (int p = 0; p < PPARTS; p++) c += g_pdeg[p * NTOT + i];
    g_norm[i] = (c > 0) ? rsqrtf((float)c) : 0.0f;
}

// ---------------------------------------------------------------------------
// h[n] = dot(features[n,:], weight) * norm[n].  Two rows per warp, 256-thread
// CTAs; streaming loads (features are read-once here).
// ---------------------------------------------------------------------------
__global__ void k_h(const float* __restrict__ feat,
                    const float* __restrict__ weight) {
    __shared__ float4 swt[DIM / 4];
    int t = threadIdx.x;
    if (t < DIM / 4) swt[t] = ((const float4*)weight)[t];
    __syncthreads();

    int warp = t >> 5, lane = t & 31;
    int row0 = (blockIdx.x * (blockDim.x >> 5) + warp) * 2;
    if (row0 >= NTOT) return;

    const float4* f0 = (const float4*)(feat + (long long)row0 * DIM);
    const float4* f1 = f0 + DIM / 4;
    float a0 = 0.f, a1 = 0.f;
#pragma unroll
    for (int k = 0; k < 4; k++) {
        float4 x = __ldcs(&f0[lane + 32 * k]);
        float4 y = __ldcs(&f1[lane + 32 * k]);
        float4 b = swt[lane + 32 * k];
        a0 += x.x * b.x + x.y * b.y + x.z * b.z + x.w * b.w;
        a1 += y.x * b.x + y.y * b.y + y.z * b.z + y.w * b.w;
    }
#pragma unroll
    for (int o = 16; o > 0; o >>= 1) {
        a0 += __shfl_down_sync(0xffffffffu, a0, o);
        a1 += __shfl_down_sync(0xffffffffu, a1, o);
    }
    if (lane == 0) {
        g_h[row0]     = a0 * g_norm[row0];
        g_h[row0 + 1] = a1 * g_norm[row0 + 1];
    }
}

// ---------------------------------------------------------------------------
// Agg partials: PPARTS CTAs per graph. h staged in shared, shared float
// accumulator, plain stores. Vectorized: 8 edges per thread per iteration.
// ---------------------------------------------------------------------------
__global__ void k_agg_part(const void* __restrict__ src,
                           const void* __restrict__ dst, long long EPG,
                           int EPP, int use16, long long E) {
    __shared__ float sh[NPG];
    __shared__ float sacc[NPG];
    __shared__ int s_is64;
    int g = blockIdx.x >> 4;
    int p = blockIdx.x & (PPARTS - 1);
    int hb = g * NPG;
    if (threadIdx.x < 32) {
        int r = warp_probe_is64(src, E);
        if (threadIdx.x == 0) s_is64 = r;
    }
    for (int j = threadIdx.x; j < NPG; j += blockDim.x) {
        sh[j] = g_h[hb + j];
        sacc[j] = 0.f;
    }
    __syncthreads();

    const int is64 = s_is64;
    long long base = (long long)g * EPG + (long long)p * EPP;
    long long rem = EPG - (long long)p * EPP;
    int cnt = (rem < (long long)EPP) ? (rem > 0 ? (int)rem : 0) : EPP;
    const int BS = 256;
    int t = threadIdx.x;
    int nfull = cnt >> 3;

    for (int gi = t; gi < nfull; gi += BS) {
        long long e0 = base + ((long long)gi << 3);
        int s[8], d[8];
        if (is64) {
            const longlong4* q = (const longlong4*)((const long long*)src + e0);
            longlong4 a = q[0], b = q[1];
            s[0] = (int)a.x & (NPG - 1); s[1] = (int)a.y & (NPG - 1);
            s[2] = (int)a.z & (NPG - 1); s[3] = (int)a.w & (NPG - 1);
            s[4] = (int)b.x & (NPG - 1); s[5] = (int)b.y & (NPG - 1);
            s[6] = (int)b.z & (NPG - 1); s[7] = (int)b.w & (NPG - 1);
        } else {
            const int4* q = (const int4*)((const int*)src + e0);
            int4 a = q[0], b = q[1];
            s[0] = a.x & (NPG - 1); s[1] = a.y & (NPG - 1);
            s[2] = a.z & (NPG - 1); s[3] = a.w & (NPG - 1);
            s[4] = b.x & (NPG - 1); s[5] = b.y & (NPG - 1);
            s[6] = b.z & (NPG - 1); s[7] = b.w & (NPG - 1);
        }
        if (use16) {
            uint4 q = *(const uint4*)(g_dst16 + e0);
            d[0] = (int)(q.x & 0xffffu); d[1] = (int)(q.x >> 16);
            d[2] = (int)(q.y & 0xffffu); d[3] = (int)(q.y >> 16);
            d[4] = (int)(q.z & 0xffffu); d[5] = (int)(q.z >> 16);
            d[6] = (int)(q.w & 0xffffu); d[7] = (int)(q.w >> 16);
        } else if (is64) {
            const longlong4* q = (const longlong4*)((const long long*)dst + e0);
            longlong4 a = q[0], b = q[1];
            d[0] = (int)a.x & (NPG - 1); d[1] = (int)a.y & (NPG - 1);
            d[2] = (int)a.z & (NPG - 1); d[3] = (int)a.w & (NPG - 1);
            d[4] = (int)b.x & (NPG - 1); d[5] = (int)b.y & (NPG - 1);
            d[6] = (int)b.z & (NPG - 1); d[7] = (int)b.w & (NPG - 1);
        } else {
            const int4* q = (const int4*)((const int*)dst + e0);
            int4 a = q[0], b = q[1];
            d[0] = a.x & (NPG - 1); d[1] = a.y & (NPG - 1);
            d[2] = a.z & (NPG - 1); d[3] = a.w & (NPG - 1);
            d[4] = b.x & (NPG - 1); d[5] = b.y & (NPG - 1);
            d[6] = b.z & (NPG - 1); d[7] = b.w & (NPG - 1);
        }
#pragma unroll
        for (int k = 0; k < 8; k++) atomicAdd(&sacc[d[k]], sh[s[k]]);
    }
    for (int e = (nfull << 3) + t; e < cnt; e += BS) {            // tail
        int si = edge_idx(src, base + e, is64) & (NPG - 1);
        int di = use16 ? (int)g_dst16[base + e]
                       : (edge_idx(dst, base + e, is64) & (NPG - 1));
        atomicAdd(&sacc[di], sh[si]);
    }
    __syncthreads();

    int out = p * NTOT + g * NPG;
    for (int j = threadIdx.x; j < NPG; j += blockDim.x)
        g_pagg[out + j] = sacc[j];
}

// ---------------------------------------------------------------------------
// Fused w + select-based top-k mask. One 1024-thread CTA per graph.
//   w_i = relu((sum agg partials)*norm + bias)
//   T   = key at stable-sort position DROPN-1 (4-pass MSD radix select)
//   keep iff key>T or (key==T and #{j<i: key_j==T} >= DROPN - #{key<T})
// Identical to rank_i = #{w_j<w_i}+#{j<i: w_j==w_i} >= DROPN.
// ---------------------------------------------------------------------------
__global__ void k_rank(const float* __restrict__ bias) {
    __shared__ int sbin[256];
    __shared__ int s_sel[2];       // [0]=prefix, [1]=remaining rank r
    __shared__ int s_wsum[32];
    __shared__ int s_nless;

    int g = blockIdx.x;
    int base = g * NPG;
    int i = threadIdx.x;           // blockDim.x == NPG == 1024
    int wid = i >> 5, lane = i & 31;

    float s = 0.f;
#pragma unroll
    for (int p = 0; p < PPARTS; p++) s += g_pagg[p * NTOT + base + i];
    float v = s * g_norm[base + i] + bias[0];
    float w = v > 0.f ? v : 0.f;
    unsigned key = __float_as_uint(w);
    if (i == 0) { s_sel[0] = 0; s_sel[1] = DROPN - 1; s_nless = 0; }
    __syncthreads();

    // ---- 4-pass MSD radix select for key at sorted rank DROPN-1 ----
#pragma unroll
    for (int pass = 3; pass >= 0; pass--) {
        int shift = pass * 8;
        if (i < 256) sbin[i] = 0;
        __syncthreads();
        unsigned prefix = (unsigned)s_sel[0];
        bool match = (pass == 3) || ((key >> (shift + 8)) == prefix);
        if (match) atomicAdd(&sbin[(key >> shift) & 255], 1);
        __syncthreads();
        if (i < 32) {               // warp 0 scans 256 bins
            int r = s_sel[1];
            int loc[8], lsum = 0;
#pragma unroll
            for (int t = 0; t < 8; t++) { loc[t] = sbin[i * 8 + t]; lsum += loc[t]; }
            int incl = lsum;
#pragma unroll
            for (int o = 1; o < 32; o <<= 1) {
                int y = __shfl_up_sync(0xffffffffu, incl, o);
                if (lane >= o) incl += y;
            }
            int excl = incl - lsum;
            bool has = (excl <= r) && (r < incl);
            if (has) {
                int rr = r - excl;
                int b = 0;
#pragma unroll
                for (int t = 0; t < 8; t++) {
                    if (rr >= loc[t] && b == t) { rr -= loc[t]; b = t + 1; }
                }
                int binfull = i * 8 + b;
                s_sel[0] = (pass == 3) ? binfull : (int)((prefix << 8) | (unsigned)binfull);
                s_sel[1] = rr;
            }
        }
        __syncthreads();
    }

    unsigned T = (unsigned)s_sel[0];

    // ---- nLess and stable position among ties ----
    unsigned lm = __ballot_sync(0xffffffffu, key < T);
    unsigned em = __ballot_sync(0xffffffffu, key == T);
    if (lane == 0) {
        atomicAdd(&s_nless, __popc(lm));
        s_wsum[wid] = __popc(em);
    }
    __syncthreads();
    if (i < 32) {                   // exclusive scan of per-warp tie counts
        int x = s_wsum[i];
        int incl = x;
#pragma unroll
        for (int o = 1; o < 32; o <<= 1) {
            int y = __shfl_up_sync(0xffffffffu, incl, o);
            if (lane >= o) incl += y;
        }
        s_wsum[i] = incl - x;
    }
    __syncthreads();

    int pos = s_wsum[wid] + __popc(em & ((1u << lane) - 1u));
    int needEq = DROPN - s_nless;
    bool keep = (key > T) || ((key == T) && (pos >= needEq));
    g_wb[base + i] = keep ? w : 0.f;
}

// ---------------------------------------------------------------------------
// out[n,:] = features[n,:] * wb[n].  2 rows per 256-thread CTA; zero rows
// skip the feature read. Streaming loads and stores (no reuse).
// ---------------------------------------------------------------------------
__global__ void k_gate(const float* __restrict__ feat,
                       float* __restrict__ out) {
    int row = blockIdx.x * 2 + (threadIdx.x >> 7);
    int col = threadIdx.x & 127;
    float wv = g_wb[row];
    const float4* fi = (const float4*)(feat + (long long)row * DIM);
    float4* fo = (float4*)(out + (long long)row * DIM);
    float4 r;
    if (wv == 0.f) {
        r = make_float4(0.f, 0.f, 0.f, 0.f);
    } else {
        float4 a = __ldcs(&fi[col]);
        r = make_float4(a.x * wv, a.y * wv, a.z * wv, a.w * wv);
    }
    __stcs(&fo[col], r);
}

// ---------------------------------------------------------------------------
extern "C" void kernel_launch(void* const* d_in, const int* in_sizes, int n_in,
                              void* d_out, int out_size) {
    const float* feat   = (const float*)d_in[0];
    const void*  src    = d_in[1];
    const void*  dst    = d_in[2];
    const float* weight = (const float*)d_in[3];
    const float* bias   = (const float*)d_in[4];
    long long E = (long long)in_sizes[1];
    long long EPG = E / BGRAPHS;
    int EPP = (int)((EPG + PPARTS - 1) / PPARTS);
    int use16 = (E <= (long long)ECAP) ? 1 : 0;

    k_deg_part<<<BGRAPHS * PPARTS, 256>>>(dst, EPG, EPP, use16, E);
    k_norm<<<NTOT / 256, 256>>>();

    k_h<<<NTOT / 16, 256>>>(feat, weight);   // 8 warps/CTA, 2 rows/warp

    k_agg_part<<<BGRAPHS * PPARTS, 256>>>(src, dst, EPG, EPP, use16, E);

    k_rank<<<BGRAPHS, NPG>>>(bias);

    k_gate<<<NTOT / 2, 256>>>(feat, (float*)d_out);
}